// round 4
// baseline (speedup 1.0000x reference)
#include <cuda_runtime.h>
#include <cuda_bf16.h>
#include <math.h>

// Problem constants
#define B_    32
#define HID_  4096
#define NH_   32
#define NKV_  8
#define HD_   128
#define BS_   16
#define MAXB_ 128
#define S_    2048
#define QKV_N 6144           // (NH + 2*NKV) * HD
#define NCHUNK 4             // flash-decode chunks of 512 keys
#define CHUNK 512
#define PART_STRIDE 528      // floats per attention partial record (16B aligned)

// ------------------------- scratch (device globals) -------------------------
// NOTE: these symbols are referenced ONLY inside device code. Passing a
// __device__ symbol from host code yields the host shadow address (silently
// "works" on GB300 via ATS but writes host memory) — that was the round-0 bug.
__device__ __align__(16) float g_fragA_hi[B_ * HID_];
__device__ __align__(16) float g_fragA_lo[B_ * HID_];
__device__ __align__(16) float g_part[2 * B_ * QKV_N];     // split-K partials (both GEMMs)
__device__ __align__(16) float g_qkv[B_ * QKV_N];          // combined + roped qkv
__device__ __align__(16) float g_attn_part[B_ * NKV_ * NCHUNK * PART_STRIDE];
__device__ __align__(16) float g_attn_out[B_ * NH_ * HD_];

// ------------------------- helpers -------------------------
__device__ __forceinline__ unsigned tf32u(float x) {
    unsigned r;
    asm("cvt.rna.tf32.f32 %0, %1;" : "=r"(r) : "f"(x));
    return r;
}

__device__ __forceinline__ void mma8(float acc[4], float4 a, unsigned b0, unsigned b1) {
    asm volatile(
        "mma.sync.aligned.m16n8k8.row.col.f32.tf32.tf32.f32 "
        "{%0,%1,%2,%3},{%4,%5,%6,%7},{%8,%9},{%0,%1,%2,%3};"
        : "+f"(acc[0]), "+f"(acc[1]), "+f"(acc[2]), "+f"(acc[3])
        : "r"(__float_as_uint(a.x)), "r"(__float_as_uint(a.y)),
          "r"(__float_as_uint(a.z)), "r"(__float_as_uint(a.w)),
          "r"(b0), "r"(b1));
}

// ------------------------- kernel 1: A fragment prep (hi/lo tf32 split) -----
// A is [32, 4096] row-major. Output layout: frag float4 index (k8*2+mt)*32+lane,
// components = (a0,a1,a2,a3) of the m16n8k8 tf32 A fragment, so the GEMM
// mainloop fetches a full warp fragment with one LDG.128.
__global__ void __launch_bounds__(256) prep_frag_kernel(const float* __restrict__ A) {
    int idx = blockIdx.x * 256 + threadIdx.x;          // 131072 total
    int i    = idx & 3;
    int lane = (idx >> 2) & 31;
    int mt   = (idx >> 7) & 1;
    int k8   = idx >> 8;
    int row = mt * 16 + (lane >> 2) + (i & 1) * 8;
    int col = k8 * 8 + (lane & 3) + (i >> 1) * 4;
    float v = A[row * HID_ + col];
    float hi = __uint_as_float(tf32u(v));
    float lo = __uint_as_float(tf32u(v - hi));
    g_fragA_hi[idx] = hi;
    g_fragA_lo[idx] = lo;
}

// prep kernel variant reading the attention output (device global)
__global__ void __launch_bounds__(256) prep_frag_attn_kernel() {
    int idx = blockIdx.x * 256 + threadIdx.x;
    int i    = idx & 3;
    int lane = (idx >> 2) & 31;
    int mt   = (idx >> 7) & 1;
    int k8   = idx >> 8;
    int row = mt * 16 + (lane >> 2) + (i & 1) * 8;
    int col = k8 * 8 + (lane & 3) + (i >> 1) * 4;
    float v = g_attn_out[row * (NH_ * HD_) + col];
    float hi = __uint_as_float(tf32u(v));
    float lo = __uint_as_float(tf32u(v - hi));
    g_fragA_hi[idx] = hi;
    g_fragA_lo[idx] = lo;
}

// ------------------------- kernel 2: 3xTF32 GEMM  C[32,N] = A[32,K] @ W[K,N]
// grid: (N/64, 2)   block: 256 threads (8 warps, each m32 x n8)
// Split-K halves write partials to g_part[kh] (device symbol, in-kernel).
__global__ void __launch_bounds__(256) gemm3tf32_kernel(
    const float* __restrict__ W, int N, int K)
{
    int w = threadIdx.x >> 5, lane = threadIdx.x & 31;
    int kh = blockIdx.y;
    int c0 = blockIdx.x * 64 + w * 8;
    int nk8 = K >> 4;                 // k8 steps per half
    int k8b = kh * nk8;

    const float* wp = W + ((size_t)(k8b * 8 + (lane & 3))) * N + c0 + (lane >> 2);
    const float4* ah = ((const float4*)g_fragA_hi) + (size_t)(k8b * 2) * 32 + lane;
    const float4* al = ((const float4*)g_fragA_lo) + (size_t)(k8b * 2) * 32 + lane;

    float acc0[4] = {0.f, 0.f, 0.f, 0.f};
    float acc1[4] = {0.f, 0.f, 0.f, 0.f};

    size_t wstep = 8 * (size_t)N;
#pragma unroll 4
    for (int i = 0; i < nk8; i++) {
        float b0f = wp[0];
        float b1f = wp[4 * N];
        wp += wstep;
        unsigned b0h = tf32u(b0f), b1h = tf32u(b1f);
        unsigned b0l = tf32u(b0f - __uint_as_float(b0h));
        unsigned b1l = tf32u(b1f - __uint_as_float(b1h));
        float4 a0h = ah[0], a1h = ah[32];
        float4 a0l = al[0], a1l = al[32];
        ah += 64; al += 64;
        mma8(acc0, a0h, b0h, b1h);
        mma8(acc0, a0l, b0h, b1h);
        mma8(acc0, a0h, b0l, b1l);
        mma8(acc1, a1h, b0h, b1h);
        mma8(acc1, a1l, b0h, b1h);
        mma8(acc1, a1h, b0l, b1l);
    }

    int r = lane >> 2;
    int c = c0 + (lane & 3) * 2;
    float* out = g_part + (size_t)kh * 32 * N;
    out[(r     ) * (size_t)N + c]     = acc0[0];
    out[(r     ) * (size_t)N + c + 1] = acc0[1];
    out[(r +  8) * (size_t)N + c]     = acc0[2];
    out[(r +  8) * (size_t)N + c + 1] = acc0[3];
    out[(r + 16) * (size_t)N + c]     = acc1[0];
    out[(r + 16) * (size_t)N + c + 1] = acc1[1];
    out[(r + 24) * (size_t)N + c]     = acc1[2];
    out[(r + 24) * (size_t)N + c + 1] = acc1[3];
}

// ------------------------- kernel 3: combine split-K + RoPE -----------------
// grid: 32 (per batch), 256 threads. Reads g_part (N=6144), writes g_qkv.
__global__ void __launch_bounds__(256) rope_combine_kernel(const int* __restrict__ positions) {
    int b = blockIdx.x;
    int pos = positions[b];
    const float* p0 = g_part + (size_t)b * QKV_N;
    const float* p1 = g_part + (size_t)B_ * QKV_N + (size_t)b * QKV_N;
    float* out = g_qkv + (size_t)b * QKV_N;

    const double LOG_THETA_OVER_HALF = 0.20503692777194265;  // ln(500000)/64
    // rope pairs: 40 heads (32 q + 8 k) x 64
    for (int p = threadIdx.x; p < 2560; p += 256) {
        int h = p >> 6, d = p & 63;
        int c1 = h * 128 + d, c2 = c1 + 64;
        float x1 = p0[c1] + p1[c1];
        float x2 = p0[c2] + p1[c2];
        double inv = exp(-(double)d * LOG_THETA_OVER_HALF);
        double f = (double)pos * inv;
        double sd, cd;
        sincos(f, &sd, &cd);
        float cs = (float)cd, sn = (float)sd;
        out[c1] = x1 * cs - x2 * sn;
        out[c2] = x2 * cs + x1 * sn;
    }
    // v passthrough
    for (int i = threadIdx.x; i < 1024; i += 256) {
        int c = 5120 + i;
        out[c] = p0[c] + p1[c];
    }
}

// ------------------------- kernel 4: attention partial (flash-decode) -------
// grid: B*NKV*NCHUNK = 1024, block 256 (8 warps, warp-per-key).
__global__ void __launch_bounds__(256) attn_partial_kernel(
    const float* __restrict__ kc, const float* __restrict__ vc,
    const int* __restrict__ positions, const int* __restrict__ bt)
{
    int x = blockIdx.x;
    int c  = x & 3;
    int kv = (x >> 2) & 7;
    int b  = x >> 5;
    int pos = positions[b];
    int L = pos + 1;
    int s0 = c * CHUNK;
    int s1 = min(s0 + CHUNK, L);
    float* pbase = g_attn_part + (size_t)x * PART_STRIDE;

    if (s0 >= s1) {
        if (threadIdx.x < 4) { pbase[threadIdx.x] = -INFINITY; pbase[4 + threadIdx.x] = 0.f; }
        for (int i = threadIdx.x; i < 512; i += 256) pbase[8 + i] = 0.f;
        return;
    }

    int w = threadIdx.x >> 5, lane = threadIdx.x & 31;
    const float4* qp = (const float4*)(g_qkv + (size_t)b * QKV_N + kv * 512);
    const float SCALE = 0.08838834764831845f;   // 1/sqrt(128)
    float4 q[4];
#pragma unroll
    for (int g = 0; g < 4; g++) {
        float4 t = qp[g * 32 + lane];
        q[g] = make_float4(t.x * SCALE, t.y * SCALE, t.z * SCALE, t.w * SCALE);
    }
    const float4* knew = (const float4*)(g_qkv + (size_t)b * QKV_N + 4096 + kv * 128);
    const float4* vnew = (const float4*)(g_qkv + (size_t)b * QKV_N + 5120 + kv * 128);
    const int* btrow = bt + b * MAXB_;

    float m[4] = {-INFINITY, -INFINITY, -INFINITY, -INFINITY};
    float l[4] = {0.f, 0.f, 0.f, 0.f};
    float4 acc[4];
#pragma unroll
    for (int g = 0; g < 4; g++) acc[g] = make_float4(0.f, 0.f, 0.f, 0.f);

    for (int s = s0 + w; s < s1; s += 8) {
        int slot = btrow[s >> 4] * 16 + (s & 15);
        const float4* kp = (s == pos) ? knew : (const float4*)(kc + (size_t)slot * 1024 + kv * 128);
        const float4* vp = (s == pos) ? vnew : (const float4*)(vc + (size_t)slot * 1024 + kv * 128);
        float4 kk = kp[lane];
        float4 vv = vp[lane];

        float ps[4];
#pragma unroll
        for (int g = 0; g < 4; g++) {
            ps[g] = fmaf(q[g].x, kk.x, fmaf(q[g].y, kk.y, fmaf(q[g].z, kk.z, q[g].w * kk.w)));
        }
#pragma unroll
        for (int off = 16; off; off >>= 1) {
#pragma unroll
            for (int g = 0; g < 4; g++) ps[g] += __shfl_xor_sync(0xffffffffu, ps[g], off);
        }
#pragma unroll
        for (int g = 0; g < 4; g++) {
            float sg = ps[g];
            if (sg > m[g]) {
                float corr = __expf(m[g] - sg);
                m[g] = sg;
                l[g] *= corr;
                acc[g].x *= corr; acc[g].y *= corr; acc[g].z *= corr; acc[g].w *= corr;
            }
            float p = __expf(sg - m[g]);
            l[g] += p;
            acc[g].x = fmaf(p, vv.x, acc[g].x);
            acc[g].y = fmaf(p, vv.y, acc[g].y);
            acc[g].z = fmaf(p, vv.z, acc[g].z);
            acc[g].w = fmaf(p, vv.w, acc[g].w);
        }
    }

    // merge 8 warps via smem
    __shared__ float sm_m[8][4];
    __shared__ float sm_l[8][4];
    __shared__ float4 sm_acc[8][4][32];
    if (lane == 0) {
#pragma unroll
        for (int g = 0; g < 4; g++) { sm_m[w][g] = m[g]; sm_l[w][g] = l[g]; }
    }
#pragma unroll
    for (int g = 0; g < 4; g++) sm_acc[w][g][lane] = acc[g];
    __syncthreads();

    if (threadIdx.x < 128) {
        int g = threadIdx.x >> 5;
        int ln = threadIdx.x & 31;
        float mm = -INFINITY;
#pragma unroll
        for (int ww = 0; ww < 8; ww++) mm = fmaxf(mm, sm_m[ww][g]);
        float ll = 0.f;
        float4 aa = make_float4(0.f, 0.f, 0.f, 0.f);
#pragma unroll
        for (int ww = 0; ww < 8; ww++) {
            float e = __expf(sm_m[ww][g] - mm);
            ll += e * sm_l[ww][g];
            float4 t = sm_acc[ww][g][ln];
            aa.x = fmaf(e, t.x, aa.x); aa.y = fmaf(e, t.y, aa.y);
            aa.z = fmaf(e, t.z, aa.z); aa.w = fmaf(e, t.w, aa.w);
        }
        if (ln == 0) { pbase[g] = mm; pbase[4 + g] = ll; }
        ((float4*)(pbase + 8))[g * 32 + ln] = aa;
    }
}

// ------------------------- kernel 5: attention combine ----------------------
// grid: B*NKV = 256, block 128
__global__ void __launch_bounds__(128) attn_combine_kernel() {
    int x = blockIdx.x;                 // b*8 + kv
    int g = threadIdx.x >> 5;
    int ln = threadIdx.x & 31;
    float mm = -INFINITY;
#pragma unroll
    for (int c = 0; c < NCHUNK; c++)
        mm = fmaxf(mm, g_attn_part[(size_t)(x * NCHUNK + c) * PART_STRIDE + g]);
    float ll = 0.f;
    float4 aa = make_float4(0.f, 0.f, 0.f, 0.f);
#pragma unroll
    for (int c = 0; c < NCHUNK; c++) {
        const float* base = g_attn_part + (size_t)(x * NCHUNK + c) * PART_STRIDE;
        float e = __expf(base[g] - mm);
        ll += e * base[4 + g];
        float4 t = ((const float4*)(base + 8))[g * 32 + ln];
        aa.x = fmaf(e, t.x, aa.x); aa.y = fmaf(e, t.y, aa.y);
        aa.z = fmaf(e, t.z, aa.z); aa.w = fmaf(e, t.w, aa.w);
    }
    float inv = 1.f / ll;
    ((float4*)g_attn_out)[(size_t)x * 128 + g * 32 + ln] =
        make_float4(aa.x * inv, aa.y * inv, aa.z * inv, aa.w * inv);
}

// ------------------------- kernel 6: final split-K add ----------------------
__global__ void __launch_bounds__(256) add_out_kernel(float* __restrict__ out) {
    int i = blockIdx.x * 256 + threadIdx.x;
    if (i < B_ * HID_) out[i] = g_part[i] + g_part[B_ * HID_ + i];
}

// ------------------------- launch ------------------------------------------
extern "C" void kernel_launch(void* const* d_in, const int* in_sizes, int n_in,
                              void* d_out, int out_size) {
    // Identify inputs by element count (robust to metadata ordering).
    // hidden 131072 | w_qkv 25165824 | w_o 16777216 | k/v cache 67108864 (x2,
    // keep encounter order) | positions/out_cache_loc 32 (x2, keep order) |
    // block_tables 4096.
    const float* hidden = 0; const float* w_qkv = 0; const float* w_o = 0;
    const float* k_cache = 0; const float* v_cache = 0;
    const int* positions = 0; const int* btables = 0;
    for (int i = 0; i < n_in; i++) {
        int sz = in_sizes[i];
        if (sz == B_ * HID_)               hidden  = (const float*)d_in[i];
        else if (sz == HID_ * QKV_N)       w_qkv   = (const float*)d_in[i];
        else if (sz == NH_ * HD_ * HID_)   w_o     = (const float*)d_in[i];
        else if (sz == 4096 * BS_ * NKV_ * HD_) {
            if (!k_cache) k_cache = (const float*)d_in[i];
            else if (!v_cache) v_cache = (const float*)d_in[i];
        }
        else if (sz == B_) { if (!positions) positions = (const int*)d_in[i]; }
        else if (sz == B_ * MAXB_)         btables = (const int*)d_in[i];
    }
    float* out = (float*)d_out;

    // 1. qkv = hidden @ w_qkv (3xTF32, split-K=2)
    prep_frag_kernel<<<512, 256>>>(hidden);
    gemm3tf32_kernel<<<dim3(QKV_N / 64, 2), 256>>>(w_qkv, QKV_N, HID_);
    // 2. combine + RoPE
    rope_combine_kernel<<<B_, 256>>>(positions);
    // 3. paged attention (flash-decode partials + combine)
    attn_partial_kernel<<<B_ * NKV_ * NCHUNK, 256>>>(k_cache, v_cache, positions, btables);
    attn_combine_kernel<<<B_ * NKV_, 128>>>();
    // 4. out = attn @ w_o
    prep_frag_attn_kernel<<<512, 256>>>();
    gemm3tf32_kernel<<<dim3(HID_ / 64, 2), 256>>>(w_o, HID_, HID_);
    add_out_kernel<<<(B_ * HID_ + 255) / 256, 256>>>(out);
}

// round 5
// speedup vs baseline: 1.9629x; 1.9629x over previous
#include <cuda_runtime.h>
#include <cuda_bf16.h>
#include <math.h>

// Problem constants
#define B_    32
#define HID_  4096
#define NH_   32
#define NKV_  8
#define HD_   128
#define BS_   16
#define MAXB_ 128
#define S_    2048
#define QKV_N 6144           // (NH + 2*NKV) * HD
#define NCHUNK 4             // flash-decode chunks of 512 keys
#define CHUNK 512
#define PART_STRIDE 528      // floats per attention partial record (16B aligned)

#define SPLITK 16
#define KSLICE 256           // K per GEMM tile (4096/16)
#define NTILE  256           // N columns per GEMM block

// ------------------------- scratch (device globals) -------------------------
// Referenced ONLY inside device code (host-side symbol decay = round-0 bug).
__device__ __align__(16) float g_part[SPLITK * B_ * QKV_N];   // split-K partials
__device__ __align__(16) float g_qkv[B_ * QKV_N];             // roped qkv
__device__ __align__(16) float g_attn_part[B_ * NKV_ * NCHUNK * PART_STRIDE];
__device__ __align__(16) float g_attn_out[B_ * NH_ * HD_];

// ------------------------- kernel 1: FFMA2 streaming GEMM -------------------
// C[32,N] = A[32,4096] @ W[4096,N].  grid (N/NTILE, SPLITK), block 128.
// Each thread: 2 n-columns, all 32 m rows, KSLICE k-steps.
// acc[mp][j] = f32x2 pair (C[2mp][n+j], C[2mp+1][n+j]).
__global__ void __launch_bounds__(128) gemm_ffma2_kernel(
    const float* __restrict__ Ain, const float* __restrict__ W, int N, int useAttn)
{
    __shared__ float sA[KSLICE * 36];   // A^T, padded stride 36 (16B aligned rows)
    const float* A = useAttn ? g_attn_out : Ain;
    int tid = threadIdx.x;
    int nb = blockIdx.x, kb = blockIdx.y;
    int k0 = kb * KSLICE;

    // stage A^T[k][m] — coalesced STS, scattered LDG (A is L2-resident, 512KB)
    {
        int m  = tid & 31;
        int q0 = tid >> 5;                    // 0..3
        const float* arow = A + m * HID_ + k0;
#pragma unroll
        for (int j = 0; j < 16; j++) {
            int qi = q0 + j * 4;              // 0..63
            float4 a = *(const float4*)(arow + qi * 4);
            int kl = qi * 4;
            sA[(kl + 0) * 36 + m] = a.x;
            sA[(kl + 1) * 36 + m] = a.y;
            sA[(kl + 2) * 36 + m] = a.z;
            sA[(kl + 3) * 36 + m] = a.w;
        }
    }
    __syncthreads();

    int n = nb * NTILE + tid * 2;
    const float2* wp = (const float2*)(W + (size_t)k0 * N) + (size_t)nb * 128 + tid;
    size_t ws = (size_t)(N >> 1);             // float2 stride per k

    unsigned long long acc[16][2];
#pragma unroll
    for (int mp = 0; mp < 16; mp++) { acc[mp][0] = 0ull; acc[mp][1] = 0ull; }

    float2 wbuf[4];
#pragma unroll
    for (int e = 0; e < 4; e++) wbuf[e] = wp[(size_t)e * ws];

    for (int k4 = 0; k4 < KSLICE / 4; k4++) {
        float2 wn[4];
        if (k4 < KSLICE / 4 - 1) {
#pragma unroll
            for (int e = 0; e < 4; e++) wn[e] = wp[(size_t)(k4 * 4 + 4 + e) * ws];
        } else {
#pragma unroll
            for (int e = 0; e < 4; e++) wn[e] = wbuf[e];
        }
#pragma unroll
        for (int e = 0; e < 4; e++) {
            int k = k4 * 4 + e;
            unsigned long long wd0, wd1;
            asm("mov.b64 %0, {%1, %1};" : "=l"(wd0) : "f"(wbuf[e].x));
            asm("mov.b64 %0, {%1, %1};" : "=l"(wd1) : "f"(wbuf[e].y));
            const ulonglong2* ap = (const ulonglong2*)(sA + k * 36);
#pragma unroll
            for (int mq = 0; mq < 8; mq++) {
                ulonglong2 aa = ap[mq];
                asm("fma.rn.f32x2 %0, %1, %2, %0;" : "+l"(acc[mq*2  ][0]) : "l"(aa.x), "l"(wd0));
                asm("fma.rn.f32x2 %0, %1, %2, %0;" : "+l"(acc[mq*2  ][1]) : "l"(aa.x), "l"(wd1));
                asm("fma.rn.f32x2 %0, %1, %2, %0;" : "+l"(acc[mq*2+1][0]) : "l"(aa.y), "l"(wd0));
                asm("fma.rn.f32x2 %0, %1, %2, %0;" : "+l"(acc[mq*2+1][1]) : "l"(aa.y), "l"(wd1));
            }
        }
#pragma unroll
        for (int e = 0; e < 4; e++) wbuf[e] = wn[e];
    }

    float* op = g_part + (size_t)kb * 32 * N + n;
#pragma unroll
    for (int mp = 0; mp < 16; mp++) {
#pragma unroll
        for (int j = 0; j < 2; j++) {
            float lo, hi;
            asm("mov.b64 {%0, %1}, %2;" : "=f"(lo), "=f"(hi) : "l"(acc[mp][j]));
            op[(size_t)(2 * mp    ) * N + j] = lo;
            op[(size_t)(2 * mp + 1) * N + j] = hi;
        }
    }
}

// ------------------------- kernel 2: combine split-K + RoPE -----------------
// grid: 32 (per batch), 256 threads.
__global__ void __launch_bounds__(256) rope_combine_kernel(const int* __restrict__ positions) {
    __shared__ float sq[QKV_N];          // 24KB combined row
    __shared__ float scs[64], ssn[64];
    int b = blockIdx.x;
    int tid = threadIdx.x;
    int pos = positions[b];

    // sum 16 partials (vectorized)
    for (int i = tid; i < QKV_N / 4; i += 256) {
        float4 s = make_float4(0.f, 0.f, 0.f, 0.f);
#pragma unroll
        for (int j = 0; j < SPLITK; j++) {
            const float4* p = (const float4*)(g_part + (size_t)j * 32 * QKV_N + (size_t)b * QKV_N);
            float4 t = p[i];
            s.x += t.x; s.y += t.y; s.z += t.z; s.w += t.w;
        }
        ((float4*)sq)[i] = s;
    }
    if (tid < 64) {
        const double LOG_THETA_OVER_HALF = 0.20503692777194265;  // ln(500000)/64
        double inv = exp(-(double)tid * LOG_THETA_OVER_HALF);
        double f = (double)pos * inv;
        double sd, cd;
        sincos(f, &sd, &cd);
        scs[tid] = (float)cd; ssn[tid] = (float)sd;
    }
    __syncthreads();

    float* out = g_qkv + (size_t)b * QKV_N;
    // rope pairs: 40 heads (32 q + 8 k) x 64
    for (int p = tid; p < 2560; p += 256) {
        int h = p >> 6, d = p & 63;
        int c1 = h * 128 + d, c2 = c1 + 64;
        float x1 = sq[c1], x2 = sq[c2];
        float cs = scs[d], sn = ssn[d];
        out[c1] = x1 * cs - x2 * sn;
        out[c2] = x2 * cs + x1 * sn;
    }
    for (int i = tid; i < 1024; i += 256) out[5120 + i] = sq[5120 + i];
}

// ------------------------- kernel 3: attention partial (flash-decode) -------
// grid: B*NKV*NCHUNK = 1024, block 256 (8 warps, warp-per-key, 2-deep pipeline)
__global__ void __launch_bounds__(256) attn_partial_kernel(
    const float* __restrict__ kc, const float* __restrict__ vc,
    const int* __restrict__ positions, const int* __restrict__ bt)
{
    int x = blockIdx.x;
    int c  = x & 3;
    int kv = (x >> 2) & 7;
    int b  = x >> 5;
    int tid = threadIdx.x;
    int pos = positions[b];
    int L = pos + 1;
    int s0 = c * CHUNK;
    int s1 = min(s0 + CHUNK, L);
    float* pbase = g_attn_part + (size_t)x * PART_STRIDE;

    if (s0 >= s1) {      // uniform per block
        if (tid < 4) { pbase[tid] = -INFINITY; pbase[4 + tid] = 0.f; }
        for (int i = tid; i < 512; i += 256) pbase[8 + i] = 0.f;
        return;
    }

    __shared__ int sbt[128];
    if (tid < 128) sbt[tid] = bt[b * MAXB_ + tid];
    __syncthreads();

    int w = tid >> 5, lane = tid & 31;
    const float4* qp = (const float4*)(g_qkv + (size_t)b * QKV_N + kv * 512);
    const float SCALE = 0.08838834764831845f;   // 1/sqrt(128)
    float4 q[4];
#pragma unroll
    for (int g = 0; g < 4; g++) {
        float4 t = qp[g * 32 + lane];
        q[g] = make_float4(t.x * SCALE, t.y * SCALE, t.z * SCALE, t.w * SCALE);
    }
    const float4* knew = (const float4*)(g_qkv + (size_t)b * QKV_N + 4096 + kv * 128);
    const float4* vnew = (const float4*)(g_qkv + (size_t)b * QKV_N + 5120 + kv * 128);

    float m[4] = {-INFINITY, -INFINITY, -INFINITY, -INFINITY};
    float l[4] = {0.f, 0.f, 0.f, 0.f};
    float4 acc[4];
#pragma unroll
    for (int g = 0; g < 4; g++) acc[g] = make_float4(0.f, 0.f, 0.f, 0.f);

    // 2-deep software pipeline over keys s, s+8, ...
    int s = s0 + w;
    float4 kkA, vvA, kkB, vvB;
    kkA = vvA = kkB = vvB = make_float4(0.f, 0.f, 0.f, 0.f);
    if (s < s1) {
        int slot = sbt[s >> 4] * 16 + (s & 15);
        const float4* kp = (s == pos) ? knew : (const float4*)(kc + (size_t)slot * 1024 + kv * 128);
        const float4* vp = (s == pos) ? vnew : (const float4*)(vc + (size_t)slot * 1024 + kv * 128);
        kkA = kp[lane]; vvA = vp[lane];
    }
    if (s + 8 < s1) {
        int sn = s + 8;
        int slot = sbt[sn >> 4] * 16 + (sn & 15);
        const float4* kp = (sn == pos) ? knew : (const float4*)(kc + (size_t)slot * 1024 + kv * 128);
        const float4* vp = (sn == pos) ? vnew : (const float4*)(vc + (size_t)slot * 1024 + kv * 128);
        kkB = kp[lane]; vvB = vp[lane];
    }

    for (; s < s1; s += 8) {
        float4 kk = kkA, vv = vvA;
        kkA = kkB; vvA = vvB;
        int sn = s + 16;
        if (sn < s1) {
            int slot = sbt[sn >> 4] * 16 + (sn & 15);
            const float4* kp = (sn == pos) ? knew : (const float4*)(kc + (size_t)slot * 1024 + kv * 128);
            const float4* vp = (sn == pos) ? vnew : (const float4*)(vc + (size_t)slot * 1024 + kv * 128);
            kkB = kp[lane]; vvB = vp[lane];
        }

        float ps[4];
#pragma unroll
        for (int g = 0; g < 4; g++)
            ps[g] = fmaf(q[g].x, kk.x, fmaf(q[g].y, kk.y, fmaf(q[g].z, kk.z, q[g].w * kk.w)));
#pragma unroll
        for (int off = 16; off; off >>= 1) {
#pragma unroll
            for (int g = 0; g < 4; g++) ps[g] += __shfl_xor_sync(0xffffffffu, ps[g], off);
        }
#pragma unroll
        for (int g = 0; g < 4; g++) {
            float sg = ps[g];
            float mn = fmaxf(m[g], sg);
            float sc = __expf(m[g] - mn);
            float p  = __expf(sg - mn);
            m[g] = mn;
            l[g] = fmaf(l[g], sc, p);
            acc[g].x = fmaf(p, vv.x, acc[g].x * sc);
            acc[g].y = fmaf(p, vv.y, acc[g].y * sc);
            acc[g].z = fmaf(p, vv.z, acc[g].z * sc);
            acc[g].w = fmaf(p, vv.w, acc[g].w * sc);
        }
    }

    // merge 8 warps via smem
    __shared__ float sm_m[8][4];
    __shared__ float sm_l[8][4];
    __shared__ float4 sm_acc[8][4][32];
    if (lane == 0) {
#pragma unroll
        for (int g = 0; g < 4; g++) { sm_m[w][g] = m[g]; sm_l[w][g] = l[g]; }
    }
#pragma unroll
    for (int g = 0; g < 4; g++) sm_acc[w][g][lane] = acc[g];
    __syncthreads();

    if (tid < 128) {
        int g = tid >> 5;
        int ln = tid & 31;
        float mm = -INFINITY;
#pragma unroll
        for (int ww = 0; ww < 8; ww++) mm = fmaxf(mm, sm_m[ww][g]);
        float ll = 0.f;
        float4 aa = make_float4(0.f, 0.f, 0.f, 0.f);
#pragma unroll
        for (int ww = 0; ww < 8; ww++) {
            float e = __expf(sm_m[ww][g] - mm);
            ll += e * sm_l[ww][g];
            float4 t = sm_acc[ww][g][ln];
            aa.x = fmaf(e, t.x, aa.x); aa.y = fmaf(e, t.y, aa.y);
            aa.z = fmaf(e, t.z, aa.z); aa.w = fmaf(e, t.w, aa.w);
        }
        if (ln == 0) { pbase[g] = mm; pbase[4 + g] = ll; }
        ((float4*)(pbase + 8))[g * 32 + ln] = aa;
    }
}

// ------------------------- kernel 4: attention combine ----------------------
// grid: B*NKV = 256, block 128
__global__ void __launch_bounds__(128) attn_combine_kernel() {
    int x = blockIdx.x;                 // b*8 + kv
    int g = threadIdx.x >> 5;
    int ln = threadIdx.x & 31;
    float mm = -INFINITY;
#pragma unroll
    for (int c = 0; c < NCHUNK; c++)
        mm = fmaxf(mm, g_attn_part[(size_t)(x * NCHUNK + c) * PART_STRIDE + g]);
    float ll = 0.f;
    float4 aa = make_float4(0.f, 0.f, 0.f, 0.f);
#pragma unroll
    for (int c = 0; c < NCHUNK; c++) {
        const float* base = g_attn_part + (size_t)(x * NCHUNK + c) * PART_STRIDE;
        float e = __expf(base[g] - mm);
        ll += e * base[4 + g];
        float4 t = ((const float4*)(base + 8))[g * 32 + ln];
        aa.x = fmaf(e, t.x, aa.x); aa.y = fmaf(e, t.y, aa.y);
        aa.z = fmaf(e, t.z, aa.z); aa.w = fmaf(e, t.w, aa.w);
    }
    float inv = 1.f / ll;
    ((float4*)g_attn_out)[(size_t)x * 128 + g * 32 + ln] =
        make_float4(aa.x * inv, aa.y * inv, aa.z * inv, aa.w * inv);
}

// ------------------------- kernel 5: final split-K reduce -------------------
__global__ void __launch_bounds__(256) add_out_kernel(float* __restrict__ out) {
    int i = blockIdx.x * 256 + threadIdx.x;       // float4 index, 32768 total
    float4 s = make_float4(0.f, 0.f, 0.f, 0.f);
#pragma unroll
    for (int j = 0; j < SPLITK; j++) {
        float4 t = ((const float4*)g_part)[(size_t)j * (B_ * HID_ / 4) + i];
        s.x += t.x; s.y += t.y; s.z += t.z; s.w += t.w;
    }
    ((float4*)out)[i] = s;
}

// ------------------------- launch ------------------------------------------
extern "C" void kernel_launch(void* const* d_in, const int* in_sizes, int n_in,
                              void* d_out, int out_size) {
    const float* hidden = 0; const float* w_qkv = 0; const float* w_o = 0;
    const float* k_cache = 0; const float* v_cache = 0;
    const int* positions = 0; const int* btables = 0;
    for (int i = 0; i < n_in; i++) {
        int sz = in_sizes[i];
        if (sz == B_ * HID_)               hidden  = (const float*)d_in[i];
        else if (sz == HID_ * QKV_N)       w_qkv   = (const float*)d_in[i];
        else if (sz == NH_ * HD_ * HID_)   w_o     = (const float*)d_in[i];
        else if (sz == 4096 * BS_ * NKV_ * HD_) {
            if (!k_cache) k_cache = (const float*)d_in[i];
            else if (!v_cache) v_cache = (const float*)d_in[i];
        }
        else if (sz == B_) { if (!positions) positions = (const int*)d_in[i]; }
        else if (sz == B_ * MAXB_)         btables = (const int*)d_in[i];
    }
    float* out = (float*)d_out;

    // 1. qkv = hidden @ w_qkv  (FFMA2 streaming, split-K=16)
    gemm_ffma2_kernel<<<dim3(QKV_N / NTILE, SPLITK), 128>>>(hidden, w_qkv, QKV_N, 0);
    // 2. combine + RoPE
    rope_combine_kernel<<<B_, 256>>>(positions);
    // 3. paged attention (flash-decode partials + combine)
    attn_partial_kernel<<<B_ * NKV_ * NCHUNK, 256>>>(k_cache, v_cache, positions, btables);
    attn_combine_kernel<<<B_ * NKV_, 128>>>();
    // 4. out = attn @ w_o
    gemm_ffma2_kernel<<<dim3(HID_ / NTILE, SPLITK), 128>>>(hidden, w_o, HID_, 1);
    add_out_kernel<<<B_ * HID_ / 4 / 256, 256>>>(out);
}

// round 6
// speedup vs baseline: 2.4777x; 1.2623x over previous
#include <cuda_runtime.h>
#include <cuda_bf16.h>
#include <math.h>

// Problem constants
#define B_    32
#define HID_  4096
#define NH_   32
#define NKV_  8
#define HD_   128
#define BS_   16
#define MAXB_ 128
#define S_    2048
#define QKV_N 6144           // (NH + 2*NKV) * HD
#define NCHUNK 8             // flash-decode chunks of 256 keys
#define CHUNK 256
#define PART_STRIDE 528      // floats per attention partial record (16B aligned)

#define SPLITK 16
#define KSLICE 256           // K per GEMM tile (4096/16)
#define NTILE  256           // N columns per GEMM block

// ------------------------- scratch (device globals) -------------------------
// Referenced ONLY inside device code (host-side symbol decay = round-0 bug).
__device__ __align__(16) float g_part[SPLITK * B_ * QKV_N];   // split-K partials
__device__ __align__(16) float g_qkv[B_ * QKV_N];             // roped qkv
__device__ __align__(16) float g_attn_part[B_ * NKV_ * NCHUNK * PART_STRIDE];
__device__ __align__(16) float g_attn_out[B_ * NH_ * HD_];

// ------------------------- kernel 1: FFMA2 streaming GEMM -------------------
// C[32,N] = A[32,4096] @ W[4096,N].  grid (N/NTILE, SPLITK), block 128.
// Each thread: 2 n-columns, all 32 m rows, KSLICE k-steps. 8-deep W prefetch
// (64B/thread in flight -> LTS-cap-bound load stream, FMA-pipe-bound compute).
__global__ void __launch_bounds__(128) gemm_ffma2_kernel(
    const float* __restrict__ Ain, const float* __restrict__ W, int N, int useAttn)
{
    __shared__ float sA[KSLICE * 36];   // A^T, padded stride 36
    const float* A = useAttn ? g_attn_out : Ain;
    int tid = threadIdx.x;
    int nb = blockIdx.x, kb = blockIdx.y;
    int k0 = kb * KSLICE;

    // stage A^T[k][m]
    {
        int m  = tid & 31;
        int q0 = tid >> 5;                    // 0..3
        const float* arow = A + m * HID_ + k0;
#pragma unroll
        for (int j = 0; j < 16; j++) {
            int qi = q0 + j * 4;              // 0..63
            float4 a = *(const float4*)(arow + qi * 4);
            int kl = qi * 4;
            sA[(kl + 0) * 36 + m] = a.x;
            sA[(kl + 1) * 36 + m] = a.y;
            sA[(kl + 2) * 36 + m] = a.z;
            sA[(kl + 3) * 36 + m] = a.w;
        }
    }
    __syncthreads();

    int n = nb * NTILE + tid * 2;
    const float2* wp = (const float2*)(W + (size_t)k0 * N) + (size_t)nb * 128 + tid;
    size_t ws = (size_t)(N >> 1);             // float2 stride per k

    unsigned long long acc[16][2];
#pragma unroll
    for (int mp = 0; mp < 16; mp++) { acc[mp][0] = 0ull; acc[mp][1] = 0ull; }

    float2 wbuf[8];
#pragma unroll
    for (int e = 0; e < 8; e++) wbuf[e] = wp[(size_t)e * ws];
    wp += 8 * ws;

    for (int it = 0; it < KSLICE / 8; it++) {
        float2 wn[8];
        if (it < KSLICE / 8 - 1) {
#pragma unroll
            for (int e = 0; e < 8; e++) wn[e] = wp[(size_t)e * ws];
        } else {
#pragma unroll
            for (int e = 0; e < 8; e++) wn[e] = wbuf[e];
        }
        wp += 8 * ws;
#pragma unroll
        for (int e = 0; e < 8; e++) {
            int k = it * 8 + e;
            unsigned long long wd0, wd1;
            asm("mov.b64 %0, {%1, %1};" : "=l"(wd0) : "f"(wbuf[e].x));
            asm("mov.b64 %0, {%1, %1};" : "=l"(wd1) : "f"(wbuf[e].y));
            const ulonglong2* ap = (const ulonglong2*)(sA + k * 36);
#pragma unroll
            for (int mq = 0; mq < 8; mq++) {
                ulonglong2 aa = ap[mq];
                asm("fma.rn.f32x2 %0, %1, %2, %0;" : "+l"(acc[mq*2  ][0]) : "l"(aa.x), "l"(wd0));
                asm("fma.rn.f32x2 %0, %1, %2, %0;" : "+l"(acc[mq*2  ][1]) : "l"(aa.x), "l"(wd1));
                asm("fma.rn.f32x2 %0, %1, %2, %0;" : "+l"(acc[mq*2+1][0]) : "l"(aa.y), "l"(wd0));
                asm("fma.rn.f32x2 %0, %1, %2, %0;" : "+l"(acc[mq*2+1][1]) : "l"(aa.y), "l"(wd1));
            }
        }
#pragma unroll
        for (int e = 0; e < 8; e++) wbuf[e] = wn[e];
    }

    float* op = g_part + (size_t)kb * 32 * N + n;
#pragma unroll
    for (int mp = 0; mp < 16; mp++) {
#pragma unroll
        for (int j = 0; j < 2; j++) {
            float lo, hi;
            asm("mov.b64 {%0, %1}, %2;" : "=f"(lo), "=f"(hi) : "l"(acc[mp][j]));
            op[(size_t)(2 * mp    ) * N + j] = lo;
            op[(size_t)(2 * mp + 1) * N + j] = hi;
        }
    }
}

// ------------------------- kernel 2: combine split-K + RoPE -----------------
// grid: 384 = 32 b x 12 col-groups of 512. block 128.
__global__ void __launch_bounds__(128) rope_combine_kernel(const int* __restrict__ positions) {
    __shared__ float sq[512];
    __shared__ float scs[64], ssn[64];
    int blk = blockIdx.x;
    int grp = blk % 12;                 // 512-col group
    int b   = blk / 12;
    int tid = threadIdx.x;
    int pos = positions[b];
    int cbase = grp * 512;

    // sum SPLITK partials for this 512-col slice (128 float4)
    {
        int i4 = cbase / 4 + tid;
        float4 s = make_float4(0.f, 0.f, 0.f, 0.f);
#pragma unroll
        for (int j = 0; j < SPLITK; j++) {
            float4 t = ((const float4*)(g_part + (size_t)j * 32 * QKV_N + (size_t)b * QKV_N))[i4];
            s.x += t.x; s.y += t.y; s.z += t.z; s.w += t.w;
        }
        ((float4*)sq)[tid] = s;
    }
    if (grp < 10 && tid < 64) {
        const double LOG_THETA_OVER_HALF = 0.20503692777194265;  // ln(500000)/64
        double inv = exp(-(double)tid * LOG_THETA_OVER_HALF);
        double f = (double)pos * inv;
        double sd, cd;
        sincos(f, &sd, &cd);
        scs[tid] = (float)cd; ssn[tid] = (float)sd;
    }
    __syncthreads();

    float* out = g_qkv + (size_t)b * QKV_N + cbase;
    if (grp < 10) {
        // 4 heads x 64 pairs = 256 pairs; 2 per thread
#pragma unroll
        for (int r = 0; r < 2; r++) {
            int p = tid + r * 128;
            int h = p >> 6, d = p & 63;
            int c1 = h * 128 + d, c2 = c1 + 64;
            float x1 = sq[c1], x2 = sq[c2];
            float cs = scs[d], sn = ssn[d];
            out[c1] = x1 * cs - x2 * sn;
            out[c2] = x2 * cs + x1 * sn;
        }
    } else {
        ((float4*)out)[tid] = ((const float4*)sq)[tid];
    }
}

// ------------------------- kernel 3: attention partial (flash-decode) -------
// grid: B*NKV*NCHUNK = 2048, block 256 (8 warps, warp-per-key, 3-deep pipeline)
__global__ void __launch_bounds__(256) attn_partial_kernel(
    const float* __restrict__ kc, const float* __restrict__ vc,
    const int* __restrict__ positions, const int* __restrict__ bt)
{
    int x = blockIdx.x;
    int c  = x & (NCHUNK - 1);
    int kv = (x >> 3) & 7;
    int b  = x >> 6;
    int tid = threadIdx.x;
    int pos = positions[b];
    int L = pos + 1;
    int s0 = c * CHUNK;
    int s1 = min(s0 + CHUNK, L);

    if (s0 >= L) return;     // empty chunk: combine skips it entirely

    float* pbase = g_attn_part + (size_t)x * PART_STRIDE;

    __shared__ int sbt[32];  // block-table slice covering this 256-key chunk
    if (tid < 32) {
        int bi = (s0 >> 4) + tid;
        sbt[tid] = (bi < MAXB_) ? bt[b * MAXB_ + bi] : 0;
    }
    __syncthreads();

    int w = tid >> 5, lane = tid & 31;
    size_t kvoff = (size_t)kv * 128;
    const float4* qp = (const float4*)(g_qkv + (size_t)b * QKV_N + kv * 512);
    const float SCALE = 0.08838834764831845f;   // 1/sqrt(128)
    float4 q[4];
#pragma unroll
    for (int g = 0; g < 4; g++) {
        float4 t = qp[g * 32 + lane];
        q[g] = make_float4(t.x * SCALE, t.y * SCALE, t.z * SCALE, t.w * SCALE);
    }
    const float4* knew = (const float4*)(g_qkv + (size_t)b * QKV_N + 4096 + kv * 128);
    const float4* vnew = (const float4*)(g_qkv + (size_t)b * QKV_N + 5120 + kv * 128);

    float m[4] = {-INFINITY, -INFINITY, -INFINITY, -INFINITY};
    float l[4] = {0.f, 0.f, 0.f, 0.f};
    float4 acc[4];
#pragma unroll
    for (int g = 0; g < 4; g++) acc[g] = make_float4(0.f, 0.f, 0.f, 0.f);

#define LOADKV(SX, KK, VV) do {                                            \
        int _s = (SX);                                                     \
        if (_s < s1) {                                                     \
            int _slot = sbt[(_s - s0) >> 4] * 16 + (_s & 15);              \
            const float4* _kp = (_s == pos) ? knew                         \
                : (const float4*)(kc + (size_t)_slot * 1024 + kvoff);      \
            const float4* _vp = (_s == pos) ? vnew                         \
                : (const float4*)(vc + (size_t)_slot * 1024 + kvoff);      \
            KK = _kp[lane]; VV = _vp[lane];                                \
        } } while (0)

    int s = s0 + w;
    float4 k0v, v0v, k1v, v1v, k2v, v2v;
    k0v = v0v = k1v = v1v = k2v = v2v = make_float4(0.f, 0.f, 0.f, 0.f);
    LOADKV(s,      k0v, v0v);
    LOADKV(s + 8,  k1v, v1v);
    LOADKV(s + 16, k2v, v2v);

#pragma unroll 3
    for (; s < s1; s += 8) {
        float4 kk = k0v, vv = v0v;
        k0v = k1v; v0v = v1v;
        k1v = k2v; v1v = v2v;
        LOADKV(s + 24, k2v, v2v);

        float ps[4];
#pragma unroll
        for (int g = 0; g < 4; g++)
            ps[g] = fmaf(q[g].x, kk.x, fmaf(q[g].y, kk.y, fmaf(q[g].z, kk.z, q[g].w * kk.w)));
#pragma unroll
        for (int off = 16; off; off >>= 1) {
#pragma unroll
            for (int g = 0; g < 4; g++) ps[g] += __shfl_xor_sync(0xffffffffu, ps[g], off);
        }
#pragma unroll
        for (int g = 0; g < 4; g++) {
            float sg = ps[g];
            float mn = fmaxf(m[g], sg);
            float sc = __expf(m[g] - mn);
            float p  = __expf(sg - mn);
            m[g] = mn;
            l[g] = fmaf(l[g], sc, p);
            acc[g].x = fmaf(p, vv.x, acc[g].x * sc);
            acc[g].y = fmaf(p, vv.y, acc[g].y * sc);
            acc[g].z = fmaf(p, vv.z, acc[g].z * sc);
            acc[g].w = fmaf(p, vv.w, acc[g].w * sc);
        }
    }
#undef LOADKV

    // merge 8 warps via smem
    __shared__ float sm_m[8][4];
    __shared__ float sm_l[8][4];
    __shared__ float4 sm_acc[8][4][32];
    if (lane == 0) {
#pragma unroll
        for (int g = 0; g < 4; g++) { sm_m[w][g] = m[g]; sm_l[w][g] = l[g]; }
    }
#pragma unroll
    for (int g = 0; g < 4; g++) sm_acc[w][g][lane] = acc[g];
    __syncthreads();

    if (tid < 128) {
        int g = tid >> 5;
        int ln = tid & 31;
        float mm = -INFINITY;
#pragma unroll
        for (int ww = 0; ww < 8; ww++) mm = fmaxf(mm, sm_m[ww][g]);
        float ll = 0.f;
        float4 aa = make_float4(0.f, 0.f, 0.f, 0.f);
#pragma unroll
        for (int ww = 0; ww < 8; ww++) {
            float e = __expf(sm_m[ww][g] - mm);
            ll += e * sm_l[ww][g];
            float4 t = sm_acc[ww][g][ln];
            aa.x = fmaf(e, t.x, aa.x); aa.y = fmaf(e, t.y, aa.y);
            aa.z = fmaf(e, t.z, aa.z); aa.w = fmaf(e, t.w, aa.w);
        }
        if (ln == 0) { pbase[g] = mm; pbase[4 + g] = ll; }
        ((float4*)(pbase + 8))[g * 32 + ln] = aa;
    }
}

// ------------------------- kernel 4: attention combine ----------------------
// grid: B*NKV = 256, block 128. Only reads chunks that contain keys.
__global__ void __launch_bounds__(128) attn_combine_kernel(const int* __restrict__ positions) {
    int x = blockIdx.x;                 // b*8 + kv
    int b = x >> 3;
    int L = positions[b] + 1;
    int nc = min(NCHUNK, (L + CHUNK - 1) / CHUNK);
    int g = threadIdx.x >> 5;
    int ln = threadIdx.x & 31;
    float mm = -INFINITY;
    for (int c = 0; c < nc; c++)
        mm = fmaxf(mm, g_attn_part[(size_t)(x * NCHUNK + c) * PART_STRIDE + g]);
    float ll = 0.f;
    float4 aa = make_float4(0.f, 0.f, 0.f, 0.f);
    for (int c = 0; c < nc; c++) {
        const float* base = g_attn_part + (size_t)(x * NCHUNK + c) * PART_STRIDE;
        float e = __expf(base[g] - mm);
        ll += e * base[4 + g];
        float4 t = ((const float4*)(base + 8))[g * 32 + ln];
        aa.x = fmaf(e, t.x, aa.x); aa.y = fmaf(e, t.y, aa.y);
        aa.z = fmaf(e, t.z, aa.z); aa.w = fmaf(e, t.w, aa.w);
    }
    float inv = 1.f / ll;
    ((float4*)g_attn_out)[(size_t)x * 128 + g * 32 + ln] =
        make_float4(aa.x * inv, aa.y * inv, aa.z * inv, aa.w * inv);
}

// ------------------------- kernel 5: final split-K reduce -------------------
__global__ void __launch_bounds__(256) add_out_kernel(float* __restrict__ out) {
    int i = blockIdx.x * 256 + threadIdx.x;       // float4 index, 32768 total
    float4 s = make_float4(0.f, 0.f, 0.f, 0.f);
#pragma unroll
    for (int j = 0; j < SPLITK; j++) {
        float4 t = ((const float4*)g_part)[(size_t)j * (B_ * HID_ / 4) + i];
        s.x += t.x; s.y += t.y; s.z += t.z; s.w += t.w;
    }
    ((float4*)out)[i] = s;
}

// ------------------------- launch ------------------------------------------
extern "C" void kernel_launch(void* const* d_in, const int* in_sizes, int n_in,
                              void* d_out, int out_size) {
    const float* hidden = 0; const float* w_qkv = 0; const float* w_o = 0;
    const float* k_cache = 0; const float* v_cache = 0;
    const int* positions = 0; const int* btables = 0;
    for (int i = 0; i < n_in; i++) {
        int sz = in_sizes[i];
        if (sz == B_ * HID_)               hidden  = (const float*)d_in[i];
        else if (sz == HID_ * QKV_N)       w_qkv   = (const float*)d_in[i];
        else if (sz == NH_ * HD_ * HID_)   w_o     = (const float*)d_in[i];
        else if (sz == 4096 * BS_ * NKV_ * HD_) {
            if (!k_cache) k_cache = (const float*)d_in[i];
            else if (!v_cache) v_cache = (const float*)d_in[i];
        }
        else if (sz == B_) { if (!positions) positions = (const int*)d_in[i]; }
        else if (sz == B_ * MAXB_)         btables = (const int*)d_in[i];
    }
    float* out = (float*)d_out;

    // 1. qkv = hidden @ w_qkv  (FFMA2 streaming, split-K=16, depth-8 prefetch)
    gemm_ffma2_kernel<<<dim3(QKV_N / NTILE, SPLITK), 128>>>(hidden, w_qkv, QKV_N, 0);
    // 2. combine + RoPE
    rope_combine_kernel<<<B_ * 12, 128>>>(positions);
    // 3. paged attention (flash-decode partials + combine)
    attn_partial_kernel<<<B_ * NKV_ * NCHUNK, 256>>>(k_cache, v_cache, positions, btables);
    attn_combine_kernel<<<B_ * NKV_, 128>>>(positions);
    // 4. out = attn @ w_o
    gemm_ffma2_kernel<<<dim3(HID_ / NTILE, SPLITK), 128>>>(hidden, w_o, HID_, 1);
    add_out_kernel<<<B_ * HID_ / 4 / 256, 256>>>(out);
}

// round 7
// speedup vs baseline: 2.6899x; 1.0856x over previous
#include <cuda_runtime.h>
#include <cuda_bf16.h>
#include <math.h>

// Problem constants
#define B_    32
#define HID_  4096
#define NH_   32
#define NKV_  8
#define HD_   128
#define BS_   16
#define MAXB_ 128
#define S_    2048
#define QKV_N 6144           // (NH + 2*NKV) * HD
#define NCHUNK 8             // flash-decode chunks of 256 keys
#define CHUNK 256
#define PART_STRIDE 528      // floats per attention partial record (16B aligned)

#define SPLITK 16
#define KSLICE 256           // K per GEMM tile (4096/16)
#define NTILE  256           // N columns per GEMM block

// ------------------------- scratch (device globals) -------------------------
// Referenced ONLY inside device code (host-side symbol decay = round-0 bug).
__device__ __align__(16) float g_part[SPLITK * B_ * QKV_N];   // split-K partials
__device__ __align__(16) float g_qkv[B_ * QKV_N];             // roped qkv
__device__ __align__(16) float g_attn_part[B_ * NKV_ * NCHUNK * PART_STRIDE];
__device__ __align__(16) float g_attn_out[B_ * NH_ * HD_];

// ------------------------- kernel 1: FFMA2 streaming GEMM -------------------
// C[32,N] = A[32,4096] @ W[4096,N].  grid (N/NTILE, SPLITK), block 128.
__global__ void __launch_bounds__(128) gemm_ffma2_kernel(
    const float* __restrict__ Ain, const float* __restrict__ W, int N, int useAttn)
{
    __shared__ float sA[KSLICE * 36];   // A^T, padded stride 36
    const float* A = useAttn ? g_attn_out : Ain;
    int tid = threadIdx.x;
    int nb = blockIdx.x, kb = blockIdx.y;
    int k0 = kb * KSLICE;

    // stage A^T[k][m]
    {
        int m  = tid & 31;
        int q0 = tid >> 5;                    // 0..3
        const float* arow = A + m * HID_ + k0;
#pragma unroll
        for (int j = 0; j < 16; j++) {
            int qi = q0 + j * 4;              // 0..63
            float4 a = *(const float4*)(arow + qi * 4);
            int kl = qi * 4;
            sA[(kl + 0) * 36 + m] = a.x;
            sA[(kl + 1) * 36 + m] = a.y;
            sA[(kl + 2) * 36 + m] = a.z;
            sA[(kl + 3) * 36 + m] = a.w;
        }
    }
    __syncthreads();

    int n = nb * NTILE + tid * 2;
    const float2* wp = (const float2*)(W + (size_t)k0 * N) + (size_t)nb * 128 + tid;
    size_t ws = (size_t)(N >> 1);             // float2 stride per k

    unsigned long long acc[16][2];
#pragma unroll
    for (int mp = 0; mp < 16; mp++) { acc[mp][0] = 0ull; acc[mp][1] = 0ull; }

    float2 wbuf[8];
#pragma unroll
    for (int e = 0; e < 8; e++) wbuf[e] = wp[(size_t)e * ws];
    wp += 8 * ws;

    for (int it = 0; it < KSLICE / 8; it++) {
        float2 wn[8];
        if (it < KSLICE / 8 - 1) {
#pragma unroll
            for (int e = 0; e < 8; e++) wn[e] = wp[(size_t)e * ws];
        } else {
#pragma unroll
            for (int e = 0; e < 8; e++) wn[e] = wbuf[e];
        }
        wp += 8 * ws;
#pragma unroll
        for (int e = 0; e < 8; e++) {
            int k = it * 8 + e;
            unsigned long long wd0, wd1;
            asm("mov.b64 %0, {%1, %1};" : "=l"(wd0) : "f"(wbuf[e].x));
            asm("mov.b64 %0, {%1, %1};" : "=l"(wd1) : "f"(wbuf[e].y));
            const ulonglong2* ap = (const ulonglong2*)(sA + k * 36);
#pragma unroll
            for (int mq = 0; mq < 8; mq++) {
                ulonglong2 aa = ap[mq];
                asm("fma.rn.f32x2 %0, %1, %2, %0;" : "+l"(acc[mq*2  ][0]) : "l"(aa.x), "l"(wd0));
                asm("fma.rn.f32x2 %0, %1, %2, %0;" : "+l"(acc[mq*2  ][1]) : "l"(aa.x), "l"(wd1));
                asm("fma.rn.f32x2 %0, %1, %2, %0;" : "+l"(acc[mq*2+1][0]) : "l"(aa.y), "l"(wd0));
                asm("fma.rn.f32x2 %0, %1, %2, %0;" : "+l"(acc[mq*2+1][1]) : "l"(aa.y), "l"(wd1));
            }
        }
#pragma unroll
        for (int e = 0; e < 8; e++) wbuf[e] = wn[e];
    }

    float* op = g_part + (size_t)kb * 32 * N + n;
#pragma unroll
    for (int mp = 0; mp < 16; mp++) {
#pragma unroll
        for (int j = 0; j < 2; j++) {
            float lo, hi;
            asm("mov.b64 {%0, %1}, %2;" : "=f"(lo), "=f"(hi) : "l"(acc[mp][j]));
            op[(size_t)(2 * mp    ) * N + j] = lo;
            op[(size_t)(2 * mp + 1) * N + j] = hi;
        }
    }
}

// ------------------------- kernel 2: combine split-K + RoPE -----------------
// grid: 384 = 32 b x 12 col-groups of 512. block 128.
__global__ void __launch_bounds__(128) rope_combine_kernel(const int* __restrict__ positions) {
    __shared__ float sq[512];
    __shared__ float scs[64], ssn[64];
    int blk = blockIdx.x;
    int grp = blk % 12;                 // 512-col group
    int b   = blk / 12;
    int tid = threadIdx.x;
    int pos = positions[b];
    int cbase = grp * 512;

    // sum SPLITK partials for this 512-col slice (128 float4)
    {
        int i4 = cbase / 4 + tid;
        float4 s = make_float4(0.f, 0.f, 0.f, 0.f);
#pragma unroll
        for (int j = 0; j < SPLITK; j++) {
            float4 t = ((const float4*)(g_part + (size_t)j * 32 * QKV_N + (size_t)b * QKV_N))[i4];
            s.x += t.x; s.y += t.y; s.z += t.z; s.w += t.w;
        }
        ((float4*)sq)[tid] = s;
    }
    if (grp < 10 && tid < 64) {
        const double LOG_THETA_OVER_HALF = 0.20503692777194265;  // ln(500000)/64
        double inv = exp(-(double)tid * LOG_THETA_OVER_HALF);
        double f = (double)pos * inv;
        double sd, cd;
        sincos(f, &sd, &cd);
        scs[tid] = (float)cd; ssn[tid] = (float)sd;
    }
    __syncthreads();

    float* out = g_qkv + (size_t)b * QKV_N + cbase;
    if (grp < 10) {
#pragma unroll
        for (int r = 0; r < 2; r++) {
            int p = tid + r * 128;
            int h = p >> 6, d = p & 63;
            int c1 = h * 128 + d, c2 = c1 + 64;
            float x1 = sq[c1], x2 = sq[c2];
            float cs = scs[d], sn = ssn[d];
            out[c1] = x1 * cs - x2 * sn;
            out[c2] = x2 * cs + x1 * sn;
        }
    } else {
        ((float4*)out)[tid] = ((const float4*)sq)[tid];
    }
}

// ------------------------- kernel 3: attention partial (flash-decode) -------
// grid: B*NKV*NCHUNK = 2048, block 256 (8 warps, warp-per-key).
// Transposed 6-shfl multi-head reduction, quad-local softmax state,
// depth-4 prefetch queue, pos-key hoisted out of the loop.
__global__ void __launch_bounds__(256, 2) attn_partial_kernel(
    const float* __restrict__ kc, const float* __restrict__ vc,
    const int* __restrict__ positions, const int* __restrict__ bt)
{
    int x = blockIdx.x;
    int c  = x & (NCHUNK - 1);
    int kv = (x >> 3) & 7;
    int b  = x >> 6;
    int tid = threadIdx.x;
    int pos = positions[b];
    int L = pos + 1;
    int s0 = c * CHUNK;
    if (s0 >= L) return;                 // empty chunk: combine skips it
    int s1 = min(s0 + CHUNK, L);
    int sEnd = min(s1, pos);             // cache keys strictly below pos
    bool hasNew = (pos < s1);            // this chunk owns the new token

    float* pbase = g_attn_part + (size_t)x * PART_STRIDE;

    __shared__ int sbt[16];              // block-table slice for 256-key chunk
    if (tid < 16) sbt[tid] = bt[b * MAXB_ + (s0 >> 4) + tid];
    __syncthreads();

    int w = tid >> 5, lane = tid & 31;
    bool b1 = (lane & 1), b2 = (lane & 2);
    size_t kvoff = (size_t)kv * 128;
    const float4* qp = (const float4*)(g_qkv + (size_t)b * QKV_N + kv * 512);
    const float SCALE = 0.08838834764831845f;   // 1/sqrt(128)
    float4 q[4];
#pragma unroll
    for (int g = 0; g < 4; g++) {
        float4 t = qp[g * 32 + lane];
        q[g] = make_float4(t.x * SCALE, t.y * SCALE, t.z * SCALE, t.w * SCALE);
    }
    const float4* knew = (const float4*)(g_qkv + (size_t)b * QKV_N + 4096 + kv * 128);
    const float4* vnew = (const float4*)(g_qkv + (size_t)b * QKV_N + 5120 + kv * 128);

    // per-lane state: head (lane&3), replicated across the 8 lanes of each residue
    float m1 = -INFINITY, l1 = 0.f;
    float4 acc[4];
#pragma unroll
    for (int g = 0; g < 4; g++) acc[g] = make_float4(0.f, 0.f, 0.f, 0.f);

#define LOADQ(I, SX) do { int _s = (SX);                                   \
        if (_s < sEnd) {                                                   \
            int _slot = sbt[(_s - s0) >> 4] * 16 + (_s & 15);              \
            kq[I] = ((const float4*)(kc + (size_t)_slot * 1024 + kvoff))[lane]; \
            vq[I] = ((const float4*)(vc + (size_t)_slot * 1024 + kvoff))[lane]; \
        } } while (0)

#define STEP(kk, vv) do {                                                  \
        float ps0 = fmaf(q[0].x, kk.x, fmaf(q[0].y, kk.y, fmaf(q[0].z, kk.z, q[0].w * kk.w))); \
        float ps1 = fmaf(q[1].x, kk.x, fmaf(q[1].y, kk.y, fmaf(q[1].z, kk.z, q[1].w * kk.w))); \
        float ps2 = fmaf(q[2].x, kk.x, fmaf(q[2].y, kk.y, fmaf(q[2].z, kk.z, q[2].w * kk.w))); \
        float ps3 = fmaf(q[3].x, kk.x, fmaf(q[3].y, kk.y, fmaf(q[3].z, kk.z, q[3].w * kk.w))); \
        float keepA = b1 ? ps1 : ps0, giveA = b1 ? ps0 : ps1;              \
        keepA += __shfl_xor_sync(0xffffffffu, giveA, 1);                   \
        float keepB = b1 ? ps3 : ps2, giveB = b1 ? ps2 : ps3;              \
        keepB += __shfl_xor_sync(0xffffffffu, giveB, 1);                   \
        float hv = b2 ? keepB : keepA, gv = b2 ? keepA : keepB;            \
        hv += __shfl_xor_sync(0xffffffffu, gv, 2);                         \
        hv += __shfl_xor_sync(0xffffffffu, hv, 4);                         \
        hv += __shfl_xor_sync(0xffffffffu, hv, 8);                         \
        hv += __shfl_xor_sync(0xffffffffu, hv, 16);                        \
        float mn  = fmaxf(m1, hv);                                         \
        float scx = __expf(m1 - mn);                                       \
        float px  = __expf(hv - mn);                                       \
        m1 = mn; l1 = fmaf(l1, scx, px);                                   \
        float pp0 = __shfl_sync(0xffffffffu, px, 0, 4);                    \
        float pp1 = __shfl_sync(0xffffffffu, px, 1, 4);                    \
        float pp2 = __shfl_sync(0xffffffffu, px, 2, 4);                    \
        float pp3 = __shfl_sync(0xffffffffu, px, 3, 4);                    \
        float ss0 = __shfl_sync(0xffffffffu, scx, 0, 4);                   \
        float ss1 = __shfl_sync(0xffffffffu, scx, 1, 4);                   \
        float ss2 = __shfl_sync(0xffffffffu, scx, 2, 4);                   \
        float ss3 = __shfl_sync(0xffffffffu, scx, 3, 4);                   \
        if (ss0 != 1.f) { acc[0].x*=ss0; acc[0].y*=ss0; acc[0].z*=ss0; acc[0].w*=ss0; } \
        if (ss1 != 1.f) { acc[1].x*=ss1; acc[1].y*=ss1; acc[1].z*=ss1; acc[1].w*=ss1; } \
        if (ss2 != 1.f) { acc[2].x*=ss2; acc[2].y*=ss2; acc[2].z*=ss2; acc[2].w*=ss2; } \
        if (ss3 != 1.f) { acc[3].x*=ss3; acc[3].y*=ss3; acc[3].z*=ss3; acc[3].w*=ss3; } \
        acc[0].x = fmaf(pp0, vv.x, acc[0].x); acc[0].y = fmaf(pp0, vv.y, acc[0].y); \
        acc[0].z = fmaf(pp0, vv.z, acc[0].z); acc[0].w = fmaf(pp0, vv.w, acc[0].w); \
        acc[1].x = fmaf(pp1, vv.x, acc[1].x); acc[1].y = fmaf(pp1, vv.y, acc[1].y); \
        acc[1].z = fmaf(pp1, vv.z, acc[1].z); acc[1].w = fmaf(pp1, vv.w, acc[1].w); \
        acc[2].x = fmaf(pp2, vv.x, acc[2].x); acc[2].y = fmaf(pp2, vv.y, acc[2].y); \
        acc[2].z = fmaf(pp2, vv.z, acc[2].z); acc[2].w = fmaf(pp2, vv.w, acc[2].w); \
        acc[3].x = fmaf(pp3, vv.x, acc[3].x); acc[3].y = fmaf(pp3, vv.y, acc[3].y); \
        acc[3].z = fmaf(pp3, vv.z, acc[3].z); acc[3].w = fmaf(pp3, vv.w, acc[3].w); \
    } while (0)

    // depth-4 queue, 4x-unrolled main loop (all conditions warp-uniform)
    float4 kq[4], vq[4];
#pragma unroll
    for (int i = 0; i < 4; i++) { kq[i] = make_float4(0,0,0,0); vq[i] = kq[i]; }
    int s = s0 + w;
    LOADQ(0, s); LOADQ(1, s + 8); LOADQ(2, s + 16); LOADQ(3, s + 24);

    for (; s < sEnd; s += 32) {
        float4 kk0 = kq[0], vv0 = vq[0]; LOADQ(0, s + 32);
        STEP(kk0, vv0);
        if (s + 8 < sEnd) {
            float4 kk1 = kq[1], vv1 = vq[1]; LOADQ(1, s + 40);
            STEP(kk1, vv1);
        }
        if (s + 16 < sEnd) {
            float4 kk2 = kq[2], vv2 = vq[2]; LOADQ(2, s + 48);
            STEP(kk2, vv2);
        }
        if (s + 24 < sEnd) {
            float4 kk3 = kq[3], vv3 = vq[3]; LOADQ(3, s + 56);
            STEP(kk3, vv3);
        }
    }

    // the new token's key/value (exactly once, by warp 0)
    if (hasNew && w == 0) {
        float4 kk = knew[lane], vv = vnew[lane];
        STEP(kk, vv);
    }
#undef LOADQ
#undef STEP

    // merge 8 warps via smem
    __shared__ float sm_m[8][4];
    __shared__ float sm_l[8][4];
    __shared__ float4 sm_acc[8][4][32];
    if (lane < 4) { sm_m[w][lane] = m1; sm_l[w][lane] = l1; }
#pragma unroll
    for (int g = 0; g < 4; g++) sm_acc[w][g][lane] = acc[g];
    __syncthreads();

    if (tid < 128) {
        int g = tid >> 5;
        int ln = tid & 31;
        float mm = -INFINITY;
#pragma unroll
        for (int ww = 0; ww < 8; ww++) mm = fmaxf(mm, sm_m[ww][g]);
        float ll = 0.f;
        float4 aa = make_float4(0.f, 0.f, 0.f, 0.f);
#pragma unroll
        for (int ww = 0; ww < 8; ww++) {
            float e = __expf(sm_m[ww][g] - mm);
            ll += e * sm_l[ww][g];
            float4 t = sm_acc[ww][g][ln];
            aa.x = fmaf(e, t.x, aa.x); aa.y = fmaf(e, t.y, aa.y);
            aa.z = fmaf(e, t.z, aa.z); aa.w = fmaf(e, t.w, aa.w);
        }
        if (ln == 0) { pbase[g] = mm; pbase[4 + g] = ll; }
        ((float4*)(pbase + 8))[g * 32 + ln] = aa;
    }
}

// ------------------------- kernel 4: attention combine ----------------------
// grid: B*NKV = 256, block 128. All chunk records loaded upfront (parallel LDG).
__global__ void __launch_bounds__(128) attn_combine_kernel(const int* __restrict__ positions) {
    int x = blockIdx.x;                 // b*8 + kv
    int b = x >> 3;
    int L = positions[b] + 1;
    int nc = min(NCHUNK, (L + CHUNK - 1) / CHUNK);
    int g = threadIdx.x >> 5;
    int ln = threadIdx.x & 31;
    const float* base0 = g_attn_part + (size_t)x * NCHUNK * PART_STRIDE;

    float mv[NCHUNK], lv[NCHUNK];
    float4 tv[NCHUNK];
#pragma unroll
    for (int c = 0; c < NCHUNK; c++) {
        const float* base = base0 + (size_t)c * PART_STRIDE;
        if (c < nc) {
            mv[c] = base[g];
            lv[c] = base[4 + g];
            tv[c] = ((const float4*)(base + 8))[g * 32 + ln];
        } else {
            mv[c] = -INFINITY; lv[c] = 0.f; tv[c] = make_float4(0.f, 0.f, 0.f, 0.f);
        }
    }
    float mm = mv[0];
#pragma unroll
    for (int c = 1; c < NCHUNK; c++) mm = fmaxf(mm, mv[c]);
    float ll = 0.f;
    float4 aa = make_float4(0.f, 0.f, 0.f, 0.f);
#pragma unroll
    for (int c = 0; c < NCHUNK; c++) {
        float e = __expf(mv[c] - mm);
        ll = fmaf(e, lv[c], ll);
        aa.x = fmaf(e, tv[c].x, aa.x); aa.y = fmaf(e, tv[c].y, aa.y);
        aa.z = fmaf(e, tv[c].z, aa.z); aa.w = fmaf(e, tv[c].w, aa.w);
    }
    float inv = 1.f / ll;
    ((float4*)g_attn_out)[(size_t)x * 128 + g * 32 + ln] =
        make_float4(aa.x * inv, aa.y * inv, aa.z * inv, aa.w * inv);
}

// ------------------------- kernel 5: final split-K reduce -------------------
__global__ void __launch_bounds__(256) add_out_kernel(float* __restrict__ out) {
    int i = blockIdx.x * 256 + threadIdx.x;       // float4 index, 32768 total
    float4 s = make_float4(0.f, 0.f, 0.f, 0.f);
#pragma unroll
    for (int j = 0; j < SPLITK; j++) {
        float4 t = ((const float4*)g_part)[(size_t)j * (B_ * HID_ / 4) + i];
        s.x += t.x; s.y += t.y; s.z += t.z; s.w += t.w;
    }
    ((float4*)out)[i] = s;
}

// ------------------------- launch ------------------------------------------
extern "C" void kernel_launch(void* const* d_in, const int* in_sizes, int n_in,
                              void* d_out, int out_size) {
    const float* hidden = 0; const float* w_qkv = 0; const float* w_o = 0;
    const float* k_cache = 0; const float* v_cache = 0;
    const int* positions = 0; const int* btables = 0;
    for (int i = 0; i < n_in; i++) {
        int sz = in_sizes[i];
        if (sz == B_ * HID_)               hidden  = (const float*)d_in[i];
        else if (sz == HID_ * QKV_N)       w_qkv   = (const float*)d_in[i];
        else if (sz == NH_ * HD_ * HID_)   w_o     = (const float*)d_in[i];
        else if (sz == 4096 * BS_ * NKV_ * HD_) {
            if (!k_cache) k_cache = (const float*)d_in[i];
            else if (!v_cache) v_cache = (const float*)d_in[i];
        }
        else if (sz == B_) { if (!positions) positions = (const int*)d_in[i]; }
        else if (sz == B_ * MAXB_)         btables = (const int*)d_in[i];
    }
    float* out = (float*)d_out;

    // 1. qkv = hidden @ w_qkv  (FFMA2 streaming, split-K=16, depth-8 prefetch)
    gemm_ffma2_kernel<<<dim3(QKV_N / NTILE, SPLITK), 128>>>(hidden, w_qkv, QKV_N, 0);
    // 2. combine + RoPE
    rope_combine_kernel<<<B_ * 12, 128>>>(positions);
    // 3. paged attention (flash-decode partials + combine)
    attn_partial_kernel<<<B_ * NKV_ * NCHUNK, 256>>>(k_cache, v_cache, positions, btables);
    attn_combine_kernel<<<B_ * NKV_, 128>>>(positions);
    // 4. out = attn @ w_o
    gemm_ffma2_kernel<<<dim3(HID_ / NTILE, SPLITK), 128>>>(hidden, w_o, HID_, 1);
    add_out_kernel<<<B_ * HID_ / 4 / 256, 256>>>(out);
}